// round 1
// baseline (speedup 1.0000x reference)
#include <cuda_runtime.h>
#include <math.h>

#define MROWS  8192            // B*L
#define DMODEL 1024
#define DINNER 2048
#define NSTATE 16
#define LLEN   2048
#define BSZ    4

// ---------------- scratch (device globals; no allocation allowed) ----------------
__device__ float g_xn[(size_t)MROWS * DMODEL];       // 32 MB  layernorm out
__device__ float g_xz[(size_t)MROWS * 2 * DINNER];   // 128 MB in-proj out [x_raw | z]
__device__ float g_xp[(size_t)MROWS * DINNER];       // 64 MB  conv+silu out
__device__ float g_dl[(size_t)MROWS * DINNER];       // 64 MB  delta (softplus)
__device__ float g_Bm[(size_t)MROWS * NSTATE];
__device__ float g_Cm[(size_t)MROWS * NSTATE];
__device__ float g_u [(size_t)MROWS * DINNER];       // 64 MB  y * silu(z)

// ---------------- fast exp (FFMA-only, no MUFU) ----------------
// exp(x) = 2^t, t = x*log2(e); round-to-nearest range reduction, deg-5 Taylor on [-.5,.5]
__device__ __forceinline__ float fexp(float x) {
    float t = x * 1.4426950408889634f;
    t = fminf(fmaxf(t, -125.f), 125.f);
    float r = rintf(t);
    int   i = (int)r;
    float f = t - r;
    float p = 1.3333558e-3f;
    p = fmaf(p, f, 9.6181291e-3f);
    p = fmaf(p, f, 5.5504109e-2f);
    p = fmaf(p, f, 2.4022651e-1f);
    p = fmaf(p, f, 6.9314718e-1f);
    p = fmaf(p, f, 1.0f);
    return __int_as_float((i + 127) << 23) * p;
}

__device__ __forceinline__ float fsilu(float x) {
    return __fdividef(x, 1.f + fexp(-x));
}

// ---------------- LayerNorm: one block per row ----------------
__global__ void __launch_bounds__(256) ln_kernel(
    const float* __restrict__ x, const float* __restrict__ w,
    const float* __restrict__ bb, float* __restrict__ xn)
{
    const int row = blockIdx.x;
    const int tid = threadIdx.x;
    const float4* xr = (const float4*)(x + (size_t)row * DMODEL);
    float4 v = xr[tid];
    float s  = v.x + v.y + v.z + v.w;
    float ss = v.x*v.x + v.y*v.y + v.z*v.z + v.w*v.w;
    #pragma unroll
    for (int o = 16; o; o >>= 1) {
        s  += __shfl_xor_sync(0xffffffffu, s,  o);
        ss += __shfl_xor_sync(0xffffffffu, ss, o);
    }
    __shared__ float rs[8], rss[8];
    int wid = tid >> 5, lane = tid & 31;
    if (!lane) { rs[wid] = s; rss[wid] = ss; }
    __syncthreads();
    if (tid == 0) {
        float S = 0.f, SS = 0.f;
        #pragma unroll
        for (int i = 0; i < 8; i++) { S += rs[i]; SS += rss[i]; }
        rs[0] = S; rss[0] = SS;
    }
    __syncthreads();
    float mean = rs[0]  * (1.f / DMODEL);
    float var  = rss[0] * (1.f / DMODEL) - mean * mean;
    float inv  = rsqrtf(var + 1e-5f);
    float4 wv = ((const float4*)w)[tid];
    float4 bv = ((const float4*)bb)[tid];
    float4 o;
    o.x = (v.x - mean) * inv * wv.x + bv.x;
    o.y = (v.y - mean) * inv * wv.y + bv.y;
    o.z = (v.z - mean) * inv * wv.z + bv.z;
    o.w = (v.w - mean) * inv * wv.w + bv.w;
    ((float4*)(xn + (size_t)row * DMODEL))[tid] = o;
}

// ---------------- Tiled SGEMM 128x128x8, 256 thr, 8x8/thread ----------------
// EPI: 0 = plain, 1 = softplus(acc + bias[col]), 2 = acc + res[row*N+col]
template <int EPI>
__global__ void __launch_bounds__(256) sgemm(
    const float* __restrict__ A, const float* __restrict__ B, float* __restrict__ C,
    int M, int N, int K,
    const float* __restrict__ bias, const float* __restrict__ res)
{
    __shared__ float As[8][132];   // [k][m], padded: conflict-free transpose store
    __shared__ float Bs[8][128];   // [k][n]
    const int tid = threadIdx.x;
    const int bm = blockIdx.y * 128;
    const int bn = blockIdx.x * 128;
    const int tx = tid & 15, ty = tid >> 4;
    const int arow = tid >> 1, acol = (tid & 1) << 2;
    const int brow = tid >> 5, bcol = (tid & 31) << 2;
    const float* Ap = A + (size_t)(bm + arow) * K + acol;
    const float* Bp = B + (size_t)brow * N + bn + bcol;

    float acc[8][8];
    #pragma unroll
    for (int i = 0; i < 8; i++)
        #pragma unroll
        for (int j = 0; j < 8; j++) acc[i][j] = 0.f;

    const int niter = K >> 3;
    for (int it = 0; it < niter; ++it) {
        float4 av = *(const float4*)Ap;
        float4 bv = *(const float4*)Bp;
        __syncthreads();
        As[acol + 0][arow] = av.x;
        As[acol + 1][arow] = av.y;
        As[acol + 2][arow] = av.z;
        As[acol + 3][arow] = av.w;
        *(float4*)&Bs[brow][bcol] = bv;
        __syncthreads();
        #pragma unroll
        for (int k = 0; k < 8; k++) {
            float a[8], b[8];
            *(float4*)&a[0] = *(const float4*)&As[k][ty * 8];
            *(float4*)&a[4] = *(const float4*)&As[k][ty * 8 + 4];
            *(float4*)&b[0] = *(const float4*)&Bs[k][tx * 8];
            *(float4*)&b[4] = *(const float4*)&Bs[k][tx * 8 + 4];
            #pragma unroll
            for (int i = 0; i < 8; i++)
                #pragma unroll
                for (int j = 0; j < 8; j++)
                    acc[i][j] = fmaf(a[i], b[j], acc[i][j]);
        }
        Ap += 8;
        Bp += (size_t)N << 3;
    }

    #pragma unroll
    for (int i = 0; i < 8; i++) {
        const int row = bm + ty * 8 + i;
        #pragma unroll
        for (int j = 0; j < 8; j++) {
            const int col = bn + tx * 8 + j;
            float v = acc[i][j];
            if (EPI == 1) {
                v += bias[col];
                v = (v > 15.f) ? v : log1pf(__expf(v));
            } else if (EPI == 2) {
                v += res[(size_t)row * N + col];
            }
            C[(size_t)row * N + col] = v;
        }
    }
}

// ---------------- depthwise causal conv (K=4) + SiLU ----------------
__global__ void __launch_bounds__(256) conv_kernel(
    const float* __restrict__ xz, const float* __restrict__ cw,
    const float* __restrict__ cb, float* __restrict__ xp)
{
    size_t idx = (size_t)blockIdx.x * 256 + threadIdx.x;
    int d = (int)(idx & (DINNER - 1));
    size_t bl = idx >> 11;                 // row = b*L + l
    int l = (int)(bl & (LLEN - 1));
    const float4 wv = *(const float4*)&cw[d * 4];
    float acc = cb[d];
    size_t base = bl * (size_t)(2 * DINNER) + d;
    acc = fmaf(xz[base], wv.w, acc);
    if (l >= 1) acc = fmaf(xz[base - 1 * 2 * DINNER], wv.z, acc);
    if (l >= 2) acc = fmaf(xz[base - 2 * 2 * DINNER], wv.y, acc);
    if (l >= 3) acc = fmaf(xz[base - 3 * 2 * DINNER], wv.x, acc);
    xp[idx] = fsilu(acc);
}

// ---------------- B and C projections (skinny GEMM, N=16+16) ----------------
__global__ void __launch_bounds__(256) bc_kernel(
    const float* __restrict__ xp, const float* __restrict__ Wb,
    const float* __restrict__ Wc, float* __restrict__ Bm, float* __restrict__ Cm)
{
    __shared__ float sW[64][32];
    __shared__ float sX[16][64];
    const int tid = threadIdx.x;
    const int row0 = blockIdx.x * 16;
    const int col = tid & 31;
    const int rg  = tid >> 5;          // 0..7
    float acc0 = 0.f, acc1 = 0.f;
    for (int k0 = 0; k0 < DINNER; k0 += 64) {
        __syncthreads();
        #pragma unroll
        for (int i = 0; i < 8; i++) {
            int e = tid * 8 + i;
            int kk = e >> 5, cc = e & 31;
            sW[kk][cc] = (cc < 16) ? Wb[(size_t)(k0 + kk) * 16 + cc]
                                   : Wc[(size_t)(k0 + kk) * 16 + cc - 16];
        }
        {
            int e = tid * 4; int r = e >> 6; int kk = e & 63;
            *(float4*)&sX[r][kk] = *(const float4*)&xp[(size_t)(row0 + r) * DINNER + k0 + kk];
        }
        __syncthreads();
        #pragma unroll
        for (int kk = 0; kk < 64; kk++) {
            float w = sW[kk][col];
            acc0 = fmaf(sX[rg][kk],     w, acc0);
            acc1 = fmaf(sX[rg + 8][kk], w, acc1);
        }
    }
    if (col < 16) {
        Bm[(size_t)(row0 + rg)     * 16 + col] = acc0;
        Bm[(size_t)(row0 + rg + 8) * 16 + col] = acc1;
    } else {
        Cm[(size_t)(row0 + rg)     * 16 + col - 16] = acc0;
        Cm[(size_t)(row0 + rg + 8) * 16 + col - 16] = acc1;
    }
}

// ---------------- selective scan, fused with y*silu(z) ----------------
// grid (BSZ, DINNER/64), 64 threads. One thread owns one (b,d), h[16] in regs.
// Double-buffered smem pipeline of 8 timesteps; 1 barrier per chunk.
__global__ void __launch_bounds__(64) scan_kernel(
    const float* __restrict__ xp, const float* __restrict__ delta,
    const float* __restrict__ Bm, const float* __restrict__ Cm,
    const float* __restrict__ A_log, const float* __restrict__ Dp,
    const float* __restrict__ xz, float* __restrict__ u)
{
    const int b  = blockIdx.x;
    const int d  = blockIdx.y * 64 + threadIdx.x;
    const int tid = threadIdx.x;

    __shared__ float sdt[2][8][64];
    __shared__ float sxt[2][8][64];
    __shared__ float sz [2][8][64];
    __shared__ float sBC[2][8][32];

    float A[NSTATE];
    #pragma unroll
    for (int n = 0; n < NSTATE; n++) A[n] = -__expf(A_log[(size_t)d * NSTATE + n]);
    float h[NSTATE];
    #pragma unroll
    for (int n = 0; n < NSTATE; n++) h[n] = 0.f;
    const float Dd = Dp[d];

    const size_t rowbase = (size_t)b * LLEN;

    // preload chunk 0
    #pragma unroll
    for (int s = 0; s < 8; s++) {
        size_t r = rowbase + s;
        sdt[0][s][tid] = delta[r * DINNER + d];
        sxt[0][s][tid] = xp[r * DINNER + d];
        sz [0][s][tid] = xz[r * (2 * DINNER) + DINNER + d];
    }
    if (tid < 32) {
        #pragma unroll
        for (int s = 0; s < 8; s++) {
            size_t r = rowbase + s;
            sBC[0][s][tid] = (tid < 16) ? Bm[r * 16 + tid] : Cm[r * 16 + tid - 16];
        }
    }
    __syncthreads();

    const int NCH = LLEN / 8;
    for (int c = 0; c < NCH; c++) {
        const int cur = c & 1, nxt = cur ^ 1;
        // prefetch next chunk into registers (LDGs in flight during compute)
        float pdt[8], pxt[8], pz[8], pbc[8];
        if (c + 1 < NCH) {
            size_t l1 = (size_t)(c + 1) * 8;
            #pragma unroll
            for (int s = 0; s < 8; s++) {
                size_t r = rowbase + l1 + s;
                pdt[s] = delta[r * DINNER + d];
                pxt[s] = xp[r * DINNER + d];
                pz[s]  = xz[r * (2 * DINNER) + DINNER + d];
            }
            if (tid < 32) {
                #pragma unroll
                for (int s = 0; s < 8; s++) {
                    size_t r = rowbase + l1 + s;
                    pbc[s] = (tid < 16) ? Bm[r * 16 + tid] : Cm[r * 16 + tid - 16];
                }
            }
        }
        // compute current chunk
        #pragma unroll
        for (int s = 0; s < 8; s++) {
            float dt = sdt[cur][s][tid];
            float xt = sxt[cur][s][tid];
            float zv = sz [cur][s][tid];
            float dx = dt * xt;
            float y = 0.f;
            #pragma unroll
            for (int n = 0; n < NSTATE; n++) {
                float ab = fexp(dt * A[n]);
                h[n] = fmaf(ab, h[n], dx * sBC[cur][s][n]);
                y = fmaf(h[n], sBC[cur][s][16 + n], y);
            }
            float yv = fmaf(Dd, xt, y);
            size_t r = rowbase + (size_t)c * 8 + s;
            u[r * DINNER + d] = yv * fsilu(zv);
        }
        // stash prefetched data into the other buffer
        if (c + 1 < NCH) {
            #pragma unroll
            for (int s = 0; s < 8; s++) {
                sdt[nxt][s][tid] = pdt[s];
                sxt[nxt][s][tid] = pxt[s];
                sz [nxt][s][tid] = pz[s];
            }
            if (tid < 32)
                #pragma unroll
                for (int s = 0; s < 8; s++) sBC[nxt][s][tid] = pbc[s];
        }
        __syncthreads();
    }
}

// ---------------- launch ----------------
extern "C" void kernel_launch(void* const* d_in, const int* in_sizes, int n_in,
                              void* d_out, int out_size)
{
    const float* x       = (const float*)d_in[0];
    const float* norm_w  = (const float*)d_in[1];
    const float* norm_b  = (const float*)d_in[2];
    const float* W_in    = (const float*)d_in[3];
    const float* conv_w  = (const float*)d_in[4];
    const float* conv_b  = (const float*)d_in[5];
    const float* A_log   = (const float*)d_in[6];
    const float* W_b     = (const float*)d_in[7];
    const float* W_c     = (const float*)d_in[8];
    const float* W_delta = (const float*)d_in[9];
    const float* b_delta = (const float*)d_in[10];
    const float* D_param = (const float*)d_in[11];
    const float* W_out   = (const float*)d_in[12];
    float* out = (float*)d_out;

    float *xn, *xz, *xp, *dl, *Bm, *Cm, *u;
    cudaGetSymbolAddress((void**)&xn, g_xn);
    cudaGetSymbolAddress((void**)&xz, g_xz);
    cudaGetSymbolAddress((void**)&xp, g_xp);
    cudaGetSymbolAddress((void**)&dl, g_dl);
    cudaGetSymbolAddress((void**)&Bm, g_Bm);
    cudaGetSymbolAddress((void**)&Cm, g_Cm);
    cudaGetSymbolAddress((void**)&u,  g_u);

    // 1) layernorm
    ln_kernel<<<MROWS, 256>>>(x, norm_w, norm_b, xn);
    // 2) in-proj: [8192,1024] @ [1024,4096]
    sgemm<0><<<dim3(2 * DINNER / 128, MROWS / 128), 256>>>(
        xn, W_in, xz, MROWS, 2 * DINNER, DMODEL, nullptr, nullptr);
    // 3) depthwise causal conv + silu
    conv_kernel<<<(MROWS * DINNER) / 256, 256>>>(xz, conv_w, conv_b, xp);
    // 4) delta: softplus([8192,2048] @ [2048,2048] + b)
    sgemm<1><<<dim3(DINNER / 128, MROWS / 128), 256>>>(
        xp, W_delta, dl, MROWS, DINNER, DINNER, b_delta, nullptr);
    // 5) B and C projections
    bc_kernel<<<MROWS / 16, 256>>>(xp, W_b, W_c, Bm, Cm);
    // 6) selective scan fused with y*silu(z)
    scan_kernel<<<dim3(BSZ, DINNER / 64), 64>>>(xp, dl, Bm, Cm, A_log, D_param, xz, u);
    // 7) out-proj + residual: [8192,2048] @ [2048,1024] + x
    sgemm<2><<<dim3(DMODEL / 128, MROWS / 128), 256>>>(
        u, W_out, out, MROWS, DMODEL, DINNER, nullptr, x);
}

// round 3
// speedup vs baseline: 6.3545x; 6.3545x over previous
#include <cuda_runtime.h>
#include <cuda_bf16.h>
#include <math.h>
#include <stdint.h>

#define MROWS  8192            // B*L
#define DMODEL 1024
#define DINNER 2048
#define NSTATE 16
#define LLEN   2048
#define BSZ    4

// ---------------- scratch (device globals; no allocation allowed) ----------------
__device__ float g_xz[(size_t)MROWS * 2 * DINNER];   // in-proj out [x_raw | z]
__device__ float g_xp[(size_t)MROWS * DINNER];       // conv+silu out (fp32, scan/bc)
__device__ float g_dl[(size_t)MROWS * DINNER];       // delta (softplus)
__device__ float g_Bm[(size_t)MROWS * NSTATE];
__device__ float g_Cm[(size_t)MROWS * NSTATE];
__device__ __nv_bfloat16 g_xn16[(size_t)MROWS * DMODEL];   // LN out (bf16)
__device__ __nv_bfloat16 g_xp16[(size_t)MROWS * DINNER];   // conv out (bf16)
__device__ __nv_bfloat16 g_u16 [(size_t)MROWS * DINNER];   // scan out (bf16)
__device__ __nv_bfloat16 g_wtin[(size_t)(2 * DINNER) * DMODEL];  // W_in^T  [4096,1024]
__device__ __nv_bfloat16 g_wtdl[(size_t)DINNER * DINNER];        // W_delta^T
__device__ __nv_bfloat16 g_wtout[(size_t)DMODEL * DINNER];       // W_out^T

// ---------------- helpers ----------------
__device__ __forceinline__ uint32_t smem_u32(const void* p) {
    uint32_t a;
    asm("{ .reg .u64 t; cvta.to.shared.u64 t, %1; cvt.u32.u64 %0, t; }" : "=r"(a) : "l"(p));
    return a;
}

#define CP_ASYNC16(dst, src) \
    asm volatile("cp.async.cg.shared.global [%0], [%1], 16;" :: "r"(dst), "l"(src))
#define CP_COMMIT() asm volatile("cp.async.commit_group;" ::: "memory")
#define CP_WAIT(n)  asm volatile("cp.async.wait_group %0;" :: "n"(n) : "memory")

#define LDSM4(r, addr) \
    asm volatile("ldmatrix.sync.aligned.m8n8.x4.shared.b16 {%0,%1,%2,%3}, [%4];" \
        : "=r"((r)[0]), "=r"((r)[1]), "=r"((r)[2]), "=r"((r)[3]) : "r"(addr))

#define MMA16816(d, a, b0, b1) \
    asm volatile("mma.sync.aligned.m16n8k16.row.col.f32.bf16.bf16.f32 " \
        "{%0,%1,%2,%3}, {%4,%5,%6,%7}, {%8,%9}, {%0,%1,%2,%3};" \
        : "+f"((d)[0]), "+f"((d)[1]), "+f"((d)[2]), "+f"((d)[3]) \
        : "r"((a)[0]), "r"((a)[1]), "r"((a)[2]), "r"((a)[3]), "r"(b0), "r"(b1))

__device__ __forceinline__ float fsilu(float x) {
    return __fdividef(x, 1.f + __expf(-x));
}

// ---------------- LayerNorm -> bf16 ----------------
__global__ void __launch_bounds__(256) ln_kernel(
    const float* __restrict__ x, const float* __restrict__ w,
    const float* __restrict__ bb, __nv_bfloat16* __restrict__ xn16)
{
    const int row = blockIdx.x;
    const int tid = threadIdx.x;
    const float4* xr = (const float4*)(x + (size_t)row * DMODEL);
    float4 v = xr[tid];
    float s  = v.x + v.y + v.z + v.w;
    float ss = v.x*v.x + v.y*v.y + v.z*v.z + v.w*v.w;
    #pragma unroll
    for (int o = 16; o; o >>= 1) {
        s  += __shfl_xor_sync(0xffffffffu, s,  o);
        ss += __shfl_xor_sync(0xffffffffu, ss, o);
    }
    __shared__ float rs[8], rss[8];
    int wid = tid >> 5, lane = tid & 31;
    if (!lane) { rs[wid] = s; rss[wid] = ss; }
    __syncthreads();
    if (tid == 0) {
        float S = 0.f, SS = 0.f;
        #pragma unroll
        for (int i = 0; i < 8; i++) { S += rs[i]; SS += rss[i]; }
        rs[0] = S; rss[0] = SS;
    }
    __syncthreads();
    float mean = rs[0]  * (1.f / DMODEL);
    float var  = rss[0] * (1.f / DMODEL) - mean * mean;
    float inv  = rsqrtf(var + 1e-5f);
    float4 wv = ((const float4*)w)[tid];
    float4 bv = ((const float4*)bb)[tid];
    float ox = (v.x - mean) * inv * wv.x + bv.x;
    float oy = (v.y - mean) * inv * wv.y + bv.y;
    float oz = (v.z - mean) * inv * wv.z + bv.z;
    float ow = (v.w - mean) * inv * wv.w + bv.w;
    __nv_bfloat162* dst = (__nv_bfloat162*)(xn16 + (size_t)row * DMODEL);
    dst[2 * tid]     = __floats2bfloat162_rn(ox, oy);
    dst[2 * tid + 1] = __floats2bfloat162_rn(oz, ow);
}

// ---------------- weight transpose + bf16 convert: W[K,N] -> Wt[N,K] ----------------
__global__ void __launch_bounds__(256) wt_kernel(
    const float* __restrict__ W, __nv_bfloat16* __restrict__ Wt, int K, int N)
{
    __shared__ float t[32][33];
    const int tid = threadIdx.x;
    const int n0 = blockIdx.x * 32;
    const int k0 = blockIdx.y * 32;
    const int tx = tid & 31, ty = tid >> 5;
    #pragma unroll
    for (int i = 0; i < 4; i++) {
        int r = ty + i * 8;
        t[r][tx] = W[(size_t)(k0 + r) * N + n0 + tx];
    }
    __syncthreads();
    #pragma unroll
    for (int i = 0; i < 4; i++) {
        int r = ty + i * 8;
        Wt[(size_t)(n0 + r) * K + k0 + tx] = __float2bfloat16(t[tx][r]);
    }
}

// ---------------- bf16 tensor-core GEMM via mma.sync ----------------
// C[M,N] = A[M,K] @ Bt[N,K]^T.  BM=BN=128, BK=64, 256 thr, warp tile 64x32.
// EPI: 0 plain, 1 softplus(acc+bias[col]), 2 acc+res.
template <int EPI>
__global__ void __launch_bounds__(256) gemm_mma(
    const __nv_bfloat16* __restrict__ A, const __nv_bfloat16* __restrict__ Bt,
    float* __restrict__ C, int M, int N, int K,
    const float* __restrict__ bias, const float* __restrict__ res)
{
    extern __shared__ char smem[];
    const uint32_t sb = smem_u32(smem);
    const int tid = threadIdx.x;
    const int lane = tid & 31, wid = tid >> 5;
    const int bm = blockIdx.y * 128, bn = blockIdx.x * 128;
    const int wm = (wid >> 2) * 64;       // 2 warps in M
    const int wn = (wid & 3) * 32;        // 4 warps in N

    // smem: A0(16K) B0(16K) A1(16K) B1(16K); rows of 128B (64 bf16), SW128 swizzle
    float acc[4][4][4];
    #pragma unroll
    for (int mt = 0; mt < 4; mt++)
        #pragma unroll
        for (int nt = 0; nt < 4; nt++)
            #pragma unroll
            for (int i = 0; i < 4; i++) acc[mt][nt][i] = 0.f;

    // per-thread load geometry (4 uint4 per tile): idx=tid+i*256, row=idx>>3, chunk=idx&7
    const int S = K >> 6;

    auto issue = [&](int s) {
        const uint32_t base = (uint32_t)(s & 1) * 32768u;
        const int k0 = s << 6;
        #pragma unroll
        for (int i = 0; i < 4; i++) {
            int idx = tid + i * 256;
            int row = idx >> 3, ch = idx & 7;
            uint32_t off = (uint32_t)row * 128u + (uint32_t)((ch * 16) ^ ((row & 7) * 16));
            CP_ASYNC16(sb + base + off,           A  + (size_t)(bm + row) * K + k0 + ch * 8);
            CP_ASYNC16(sb + base + 16384u + off,  Bt + (size_t)(bn + row) * K + k0 + ch * 8);
        }
        CP_COMMIT();
    };

    issue(0);
    if (S > 1) issue(1);

    const int lrow = lane & 15;
    const int lkhi = (lane >> 4) * 16;    // bytes

    for (int s = 0; s < S; s++) {
        if (s + 2 <= S) { CP_WAIT(1); } else { CP_WAIT(0); }
        __syncthreads();
        const uint32_t Ab = sb + (uint32_t)(s & 1) * 32768u;
        const uint32_t Bb = Ab + 16384u;
        #pragma unroll
        for (int k = 0; k < 4; k++) {
            const int kb = k * 32;        // bytes within 128B row
            uint32_t a[4][4], b[2][4];
            #pragma unroll
            for (int mt = 0; mt < 4; mt++) {
                int row = wm + mt * 16 + lrow;
                uint32_t addr = Ab + (uint32_t)row * 128u
                              + (uint32_t)((kb + lkhi) ^ ((row & 7) * 16));
                LDSM4(a[mt], addr);
            }
            #pragma unroll
            for (int np = 0; np < 2; np++) {
                int row = wn + np * 16 + lrow;
                uint32_t addr = Bb + (uint32_t)row * 128u
                              + (uint32_t)((kb + lkhi) ^ ((row & 7) * 16));
                LDSM4(b[np], addr);
            }
            #pragma unroll
            for (int mt = 0; mt < 4; mt++)
                #pragma unroll
                for (int nt = 0; nt < 4; nt++) {
                    const int np = nt >> 1, sel = nt & 1;
                    MMA16816(acc[mt][nt], a[mt], b[np][sel], b[np][sel + 2]);
                }
        }
        __syncthreads();
        if (s + 2 < S) issue(s + 2);
    }

    // epilogue: direct float2 stores
    #pragma unroll
    for (int mt = 0; mt < 4; mt++) {
        const int r0 = bm + wm + mt * 16 + (lane >> 2);
        #pragma unroll
        for (int nt = 0; nt < 4; nt++) {
            const int c = bn + wn + nt * 8 + (lane & 3) * 2;
            float vx0 = acc[mt][nt][0], vy0 = acc[mt][nt][1];
            float vx1 = acc[mt][nt][2], vy1 = acc[mt][nt][3];
            if (EPI == 1) {
                float2 bvv = *(const float2*)&bias[c];
                vx0 += bvv.x; vy0 += bvv.y; vx1 += bvv.x; vy1 += bvv.y;
                vx0 = (vx0 > 15.f) ? vx0 : log1pf(__expf(vx0));
                vy0 = (vy0 > 15.f) ? vy0 : log1pf(__expf(vy0));
                vx1 = (vx1 > 15.f) ? vx1 : log1pf(__expf(vx1));
                vy1 = (vy1 > 15.f) ? vy1 : log1pf(__expf(vy1));
            } else if (EPI == 2) {
                float2 r0v = *(const float2*)&res[(size_t)r0 * N + c];
                float2 r1v = *(const float2*)&res[(size_t)(r0 + 8) * N + c];
                vx0 += r0v.x; vy0 += r0v.y; vx1 += r1v.x; vy1 += r1v.y;
            }
            *(float2*)&C[(size_t)r0 * N + c]       = make_float2(vx0, vy0);
            *(float2*)&C[(size_t)(r0 + 8) * N + c] = make_float2(vx1, vy1);
        }
    }
}

// ---------------- depthwise causal conv (K=4) + SiLU -> fp32 + bf16 ----------------
__global__ void __launch_bounds__(256) conv_kernel(
    const float* __restrict__ xz, const float* __restrict__ cw,
    const float* __restrict__ cb, float* __restrict__ xp,
    __nv_bfloat16* __restrict__ xp16)
{
    size_t idx = (size_t)blockIdx.x * 256 + threadIdx.x;
    int d = (int)(idx & (DINNER - 1));
    size_t bl = idx >> 11;
    int l = (int)(bl & (LLEN - 1));
    const float4 wv = *(const float4*)&cw[d * 4];
    float acc = cb[d];
    size_t base = bl * (size_t)(2 * DINNER) + d;
    acc = fmaf(xz[base], wv.w, acc);
    if (l >= 1) acc = fmaf(xz[base - 1 * 2 * DINNER], wv.z, acc);
    if (l >= 2) acc = fmaf(xz[base - 2 * 2 * DINNER], wv.y, acc);
    if (l >= 3) acc = fmaf(xz[base - 3 * 2 * DINNER], wv.x, acc);
    float v = fsilu(acc);
    xp[idx] = v;
    xp16[idx] = __float2bfloat16(v);
}

// ---------------- B and C projections (skinny GEMM, N=16+16, fp32) ----------------
__global__ void __launch_bounds__(256) bc_kernel(
    const float* __restrict__ xp, const float* __restrict__ Wb,
    const float* __restrict__ Wc, float* __restrict__ Bm, float* __restrict__ Cm)
{
    __shared__ float sW[64][32];
    __shared__ float sX[16][64];
    const int tid = threadIdx.x;
    const int row0 = blockIdx.x * 16;
    const int col = tid & 31;
    const int rg  = tid >> 5;
    float acc0 = 0.f, acc1 = 0.f;
    for (int k0 = 0; k0 < DINNER; k0 += 64) {
        __syncthreads();
        #pragma unroll
        for (int i = 0; i < 8; i++) {
            int e = tid * 8 + i;
            int kk = e >> 5, cc = e & 31;
            sW[kk][cc] = (cc < 16) ? Wb[(size_t)(k0 + kk) * 16 + cc]
                                   : Wc[(size_t)(k0 + kk) * 16 + cc - 16];
        }
        {
            int e = tid * 4; int r = e >> 6; int kk = e & 63;
            *(float4*)&sX[r][kk] = *(const float4*)&xp[(size_t)(row0 + r) * DINNER + k0 + kk];
        }
        __syncthreads();
        #pragma unroll
        for (int kk = 0; kk < 64; kk++) {
            float w = sW[kk][col];
            acc0 = fmaf(sX[rg][kk],     w, acc0);
            acc1 = fmaf(sX[rg + 8][kk], w, acc1);
        }
    }
    if (col < 16) {
        Bm[(size_t)(row0 + rg)     * 16 + col] = acc0;
        Bm[(size_t)(row0 + rg + 8) * 16 + col] = acc1;
    } else {
        Cm[(size_t)(row0 + rg)     * 16 + col - 16] = acc0;
        Cm[(size_t)(row0 + rg + 8) * 16 + col - 16] = acc1;
    }
}

// ---------------- selective scan, fused with y*silu(z) -> bf16 u ----------------
__global__ void __launch_bounds__(64) scan_kernel(
    const float* __restrict__ xp, const float* __restrict__ delta,
    const float* __restrict__ Bm, const float* __restrict__ Cm,
    const float* __restrict__ A_log, const float* __restrict__ Dp,
    const float* __restrict__ xz, __nv_bfloat16* __restrict__ u)
{
    const int b  = blockIdx.x;
    const int d  = blockIdx.y * 64 + threadIdx.x;
    const int tid = threadIdx.x;

    __shared__ float sdt[2][8][64];
    __shared__ float sxt[2][8][64];
    __shared__ float sz [2][8][64];
    __shared__ float sBC[2][8][32];

    float A[NSTATE];
    #pragma unroll
    for (int n = 0; n < NSTATE; n++) A[n] = -__expf(A_log[(size_t)d * NSTATE + n]);
    float h[NSTATE];
    #pragma unroll
    for (int n = 0; n < NSTATE; n++) h[n] = 0.f;
    const float Dd = Dp[d];

    const size_t rowbase = (size_t)b * LLEN;

    #pragma unroll
    for (int s = 0; s < 8; s++) {
        size_t r = rowbase + s;
        sdt[0][s][tid] = delta[r * DINNER + d];
        sxt[0][s][tid] = xp[r * DINNER + d];
        sz [0][s][tid] = xz[r * (2 * DINNER) + DINNER + d];
    }
    if (tid < 32) {
        #pragma unroll
        for (int s = 0; s < 8; s++) {
            size_t r = rowbase + s;
            sBC[0][s][tid] = (tid < 16) ? Bm[r * 16 + tid] : Cm[r * 16 + tid - 16];
        }
    }
    __syncthreads();

    const int NCH = LLEN / 8;
    for (int c = 0; c < NCH; c++) {
        const int cur = c & 1, nxt = cur ^ 1;
        float pdt[8], pxt[8], pz[8], pbc[8];
        if (c + 1 < NCH) {
            size_t l1 = (size_t)(c + 1) * 8;
            #pragma unroll
            for (int s = 0; s < 8; s++) {
                size_t r = rowbase + l1 + s;
                pdt[s] = delta[r * DINNER + d];
                pxt[s] = xp[r * DINNER + d];
                pz[s]  = xz[r * (2 * DINNER) + DINNER + d];
            }
            if (tid < 32) {
                #pragma unroll
                for (int s = 0; s < 8; s++) {
                    size_t r = rowbase + l1 + s;
                    pbc[s] = (tid < 16) ? Bm[r * 16 + tid] : Cm[r * 16 + tid - 16];
                }
            }
        }
        #pragma unroll
        for (int s = 0; s < 8; s++) {
            float dt = sdt[cur][s][tid];
            float xt = sxt[cur][s][tid];
            float zv = sz [cur][s][tid];
            float dx = dt * xt;
            float y = 0.f;
            #pragma unroll
            for (int n = 0; n < NSTATE; n++) {
                float ab = __expf(dt * A[n]);
                h[n] = fmaf(ab, h[n], dx * sBC[cur][s][n]);
                y = fmaf(h[n], sBC[cur][s][16 + n], y);
            }
            float yv = fmaf(Dd, xt, y);
            size_t r = rowbase + (size_t)c * 8 + s;
            u[r * DINNER + d] = __float2bfloat16(yv * fsilu(zv));
        }
        if (c + 1 < NCH) {
            #pragma unroll
            for (int s = 0; s < 8; s++) {
                sdt[nxt][s][tid] = pdt[s];
                sxt[nxt][s][tid] = pxt[s];
                sz [nxt][s][tid] = pz[s];
            }
            if (tid < 32)
                #pragma unroll
                for (int s = 0; s < 8; s++) sBC[nxt][s][tid] = pbc[s];
        }
        __syncthreads();
    }
}

// ---------------- launch ----------------
#define GEMM_SMEM 65536   // 2 stages x (16KB A + 16KB B)

extern "C" void kernel_launch(void* const* d_in, const int* in_sizes, int n_in,
                              void* d_out, int out_size)
{
    const float* x       = (const float*)d_in[0];
    const float* norm_w  = (const float*)d_in[1];
    const float* norm_b  = (const float*)d_in[2];
    const float* W_in    = (const float*)d_in[3];
    const float* conv_w  = (const float*)d_in[4];
    const float* conv_b  = (const float*)d_in[5];
    const float* A_log   = (const float*)d_in[6];
    const float* W_b     = (const float*)d_in[7];
    const float* W_c     = (const float*)d_in[8];
    const float* W_delta = (const float*)d_in[9];
    const float* b_delta = (const float*)d_in[10];
    const float* D_param = (const float*)d_in[11];
    const float* W_out   = (const float*)d_in[12];
    float* out = (float*)d_out;

    float *xz, *xp, *dl, *Bm, *Cm;
    __nv_bfloat16 *xn16, *xp16, *u16, *wtin, *wtdl, *wtout;
    cudaGetSymbolAddress((void**)&xz, g_xz);
    cudaGetSymbolAddress((void**)&xp, g_xp);
    cudaGetSymbolAddress((void**)&dl, g_dl);
    cudaGetSymbolAddress((void**)&Bm, g_Bm);
    cudaGetSymbolAddress((void**)&Cm, g_Cm);
    cudaGetSymbolAddress((void**)&xn16, g_xn16);
    cudaGetSymbolAddress((void**)&xp16, g_xp16);
    cudaGetSymbolAddress((void**)&u16, g_u16);
    cudaGetSymbolAddress((void**)&wtin, g_wtin);
    cudaGetSymbolAddress((void**)&wtdl, g_wtdl);
    cudaGetSymbolAddress((void**)&wtout, g_wtout);

    cudaFuncSetAttribute(gemm_mma<0>, cudaFuncAttributeMaxDynamicSharedMemorySize, GEMM_SMEM);
    cudaFuncSetAttribute(gemm_mma<1>, cudaFuncAttributeMaxDynamicSharedMemorySize, GEMM_SMEM);
    cudaFuncSetAttribute(gemm_mma<2>, cudaFuncAttributeMaxDynamicSharedMemorySize, GEMM_SMEM);

    // 0) weight transpose + convert to bf16
    wt_kernel<<<dim3(2 * DINNER / 32, DMODEL / 32), 256>>>(W_in, wtin, DMODEL, 2 * DINNER);
    wt_kernel<<<dim3(DINNER / 32, DINNER / 32), 256>>>(W_delta, wtdl, DINNER, DINNER);
    wt_kernel<<<dim3(DMODEL / 32, DINNER / 32), 256>>>(W_out, wtout, DINNER, DMODEL);

    // 1) layernorm (bf16 out)
    ln_kernel<<<MROWS, 256>>>(x, norm_w, norm_b, xn16);
    // 2) in-proj: [8192,1024] @ [1024,4096] -> xz fp32
    gemm_mma<0><<<dim3(2 * DINNER / 128, MROWS / 128), 256, GEMM_SMEM>>>(
        xn16, wtin, xz, MROWS, 2 * DINNER, DMODEL, nullptr, nullptr);
    // 3) depthwise causal conv + silu
    conv_kernel<<<(MROWS * DINNER) / 256, 256>>>(xz, conv_w, conv_b, xp, xp16);
    // 4) delta: softplus([8192,2048] @ [2048,2048] + b)
    gemm_mma<1><<<dim3(DINNER / 128, MROWS / 128), 256, GEMM_SMEM>>>(
        xp16, wtdl, dl, MROWS, DINNER, DINNER, b_delta, nullptr);
    // 5) B and C projections
    bc_kernel<<<MROWS / 16, 256>>>(xp, W_b, W_c, Bm, Cm);
    // 6) selective scan fused with y*silu(z) -> bf16 u
    scan_kernel<<<dim3(BSZ, DINNER / 64), 64>>>(xp, dl, Bm, Cm, A_log, D_param, xz, u16);
    // 7) out-proj + residual: [8192,2048] @ [2048,1024] + x
    gemm_mma<2><<<dim3(DMODEL / 128, MROWS / 128), 256, GEMM_SMEM>>>(
        u16, wtout, out, MROWS, DMODEL, DINNER, nullptr, x);
}

// round 4
// speedup vs baseline: 6.4565x; 1.0160x over previous
#include <cuda_runtime.h>
#include <cuda_bf16.h>
#include <math.h>
#include <stdint.h>

#define MROWS  8192            // B*L
#define DMODEL 1024
#define DINNER 2048
#define NSTATE 16
#define LLEN   2048
#define BSZ    4

// ---------------- scratch (device globals) ----------------
__device__ float g_xz[(size_t)MROWS * 2 * DINNER];   // in-proj out [x_raw | z]
__device__ float g_xp[(size_t)MROWS * DINNER];       // conv+silu out (fp32)
__device__ float g_dl[(size_t)MROWS * DINNER];       // delta (softplus)
__device__ float g_Bm[(size_t)MROWS * NSTATE];
__device__ float g_Cm[(size_t)MROWS * NSTATE];
__device__ __nv_bfloat16 g_xn16[(size_t)MROWS * DMODEL];
__device__ __nv_bfloat16 g_xp16[(size_t)MROWS * DINNER];
__device__ __nv_bfloat16 g_u16 [(size_t)MROWS * DINNER];
__device__ __nv_bfloat16 g_wtin[(size_t)(2 * DINNER) * DMODEL];
__device__ __nv_bfloat16 g_wtdl[(size_t)DINNER * DINNER];
__device__ __nv_bfloat16 g_wtout[(size_t)DMODEL * DINNER];

// ---------------- helpers ----------------
__device__ __forceinline__ uint32_t smem_u32(const void* p) {
    uint32_t a;
    asm("{ .reg .u64 t; cvta.to.shared.u64 t, %1; cvt.u32.u64 %0, t; }" : "=r"(a) : "l"(p));
    return a;
}

#define CP_ASYNC16(dst, src) \
    asm volatile("cp.async.cg.shared.global [%0], [%1], 16;" :: "r"(dst), "l"(src))
#define CP_COMMIT() asm volatile("cp.async.commit_group;" ::: "memory")
#define CP_WAIT(n)  asm volatile("cp.async.wait_group %0;" :: "n"(n) : "memory")

#define LDSM4(r, addr) \
    asm volatile("ldmatrix.sync.aligned.m8n8.x4.shared.b16 {%0,%1,%2,%3}, [%4];" \
        : "=r"((r)[0]), "=r"((r)[1]), "=r"((r)[2]), "=r"((r)[3]) : "r"(addr))

#define MMA16816(d, a, b0, b1) \
    asm volatile("mma.sync.aligned.m16n8k16.row.col.f32.bf16.bf16.f32 " \
        "{%0,%1,%2,%3}, {%4,%5,%6,%7}, {%8,%9}, {%0,%1,%2,%3};" \
        : "+f"((d)[0]), "+f"((d)[1]), "+f"((d)[2]), "+f"((d)[3]) \
        : "r"((a)[0]), "r"((a)[1]), "r"((a)[2]), "r"((a)[3]), "r"(b0), "r"(b1))

__device__ __forceinline__ float fsilu(float x) {
    return __fdividef(x, 1.f + __expf(-x));
}

// ---------------- LayerNorm -> bf16 ----------------
__global__ void __launch_bounds__(256) ln_kernel(
    const float* __restrict__ x, const float* __restrict__ w,
    const float* __restrict__ bb, __nv_bfloat16* __restrict__ xn16)
{
    const int row = blockIdx.x;
    const int tid = threadIdx.x;
    const float4* xr = (const float4*)(x + (size_t)row * DMODEL);
    float4 v = xr[tid];
    float s  = v.x + v.y + v.z + v.w;
    float ss = v.x*v.x + v.y*v.y + v.z*v.z + v.w*v.w;
    #pragma unroll
    for (int o = 16; o; o >>= 1) {
        s  += __shfl_xor_sync(0xffffffffu, s,  o);
        ss += __shfl_xor_sync(0xffffffffu, ss, o);
    }
    __shared__ float rs[8], rss[8];
    int wid = tid >> 5, lane = tid & 31;
    if (!lane) { rs[wid] = s; rss[wid] = ss; }
    __syncthreads();
    if (tid == 0) {
        float S = 0.f, SS = 0.f;
        #pragma unroll
        for (int i = 0; i < 8; i++) { S += rs[i]; SS += rss[i]; }
        rs[0] = S; rss[0] = SS;
    }
    __syncthreads();
    float mean = rs[0]  * (1.f / DMODEL);
    float var  = rss[0] * (1.f / DMODEL) - mean * mean;
    float inv  = rsqrtf(var + 1e-5f);
    float4 wv = ((const float4*)w)[tid];
    float4 bv = ((const float4*)bb)[tid];
    float ox = (v.x - mean) * inv * wv.x + bv.x;
    float oy = (v.y - mean) * inv * wv.y + bv.y;
    float oz = (v.z - mean) * inv * wv.z + bv.z;
    float ow = (v.w - mean) * inv * wv.w + bv.w;
    __nv_bfloat162* dst = (__nv_bfloat162*)(xn16 + (size_t)row * DMODEL);
    dst[2 * tid]     = __floats2bfloat162_rn(ox, oy);
    dst[2 * tid + 1] = __floats2bfloat162_rn(oz, ow);
}

// ---------------- weight transpose + bf16: W[K,N] -> Wt[N,K] ----------------
__global__ void __launch_bounds__(256) wt_kernel(
    const float* __restrict__ W, __nv_bfloat16* __restrict__ Wt, int K, int N)
{
    __shared__ float t[32][33];
    const int tid = threadIdx.x;
    const int n0 = blockIdx.x * 32;
    const int k0 = blockIdx.y * 32;
    const int tx = tid & 31, ty = tid >> 5;
    #pragma unroll
    for (int i = 0; i < 4; i++) {
        int r = ty + i * 8;
        t[r][tx] = W[(size_t)(k0 + r) * N + n0 + tx];
    }
    __syncthreads();
    #pragma unroll
    for (int i = 0; i < 4; i++) {
        int r = ty + i * 8;
        Wt[(size_t)(n0 + r) * K + k0 + tx] = __float2bfloat16(t[tx][r]);
    }
}

// ---------------- bf16 mma.sync GEMM, CTA 128x256x64, warp 64x64, 4-stage ----------------
// C[M,N] = A[M,K] @ Bt[N,K]^T.  EPI: 0 plain, 1 softplus(acc+bias[col]), 2 acc+res.
#define STAGE_BYTES 49152u     // 16KB A + 32KB B
template <int EPI>
__global__ void __launch_bounds__(256) gemm_mma(
    const __nv_bfloat16* __restrict__ A, const __nv_bfloat16* __restrict__ Bt,
    float* __restrict__ C, int M, int N, int K,
    const float* __restrict__ bias, const float* __restrict__ res)
{
    extern __shared__ char smem[];
    const uint32_t sb = smem_u32(smem);
    const int tid = threadIdx.x;
    const int lane = tid & 31, wid = tid >> 5;
    const int bm = blockIdx.y * 128, bn = blockIdx.x * 256;
    const int wm = (wid & 1) * 64;        // 2 warps in M
    const int wn = (wid >> 1) * 64;       // 4 warps in N

    float acc[4][8][4];
    #pragma unroll
    for (int mt = 0; mt < 4; mt++)
        #pragma unroll
        for (int nt = 0; nt < 8; nt++)
            #pragma unroll
            for (int i = 0; i < 4; i++) acc[mt][nt][i] = 0.f;

    const int S = K >> 6;

    auto issue = [&](int s) {
        const uint32_t base = (uint32_t)(s & 3) * STAGE_BYTES;
        const int k0 = s << 6;
        #pragma unroll
        for (int i = 0; i < 4; i++) {            // A: 128 rows
            int idx = tid + i * 256;
            int row = idx >> 3, ch = idx & 7;
            uint32_t off = (uint32_t)row * 128u + (uint32_t)((ch * 16) ^ ((row & 7) * 16));
            CP_ASYNC16(sb + base + off, A + (size_t)(bm + row) * K + k0 + ch * 8);
        }
        #pragma unroll
        for (int i = 0; i < 8; i++) {            // B: 256 rows
            int idx = tid + i * 256;
            int row = idx >> 3, ch = idx & 7;
            uint32_t off = (uint32_t)row * 128u + (uint32_t)((ch * 16) ^ ((row & 7) * 16));
            CP_ASYNC16(sb + base + 16384u + off, Bt + (size_t)(bn + row) * K + k0 + ch * 8);
        }
        CP_COMMIT();
    };

    issue(0); issue(1); issue(2);

    const int lrow = lane & 15;
    const int lkhi = (lane >> 4) * 16;    // bytes

    for (int s = 0; s < S; s++) {
        CP_WAIT(2);
        __syncthreads();
        if (s + 3 < S) issue(s + 3);      // refills buffer (s-1)&3, free after barrier
        const uint32_t Ab = sb + (uint32_t)(s & 3) * STAGE_BYTES;
        const uint32_t Bb = Ab + 16384u;
        #pragma unroll
        for (int k = 0; k < 4; k++) {
            const int kb = k * 32;
            uint32_t a[4][4], b[4][4];
            #pragma unroll
            for (int mt = 0; mt < 4; mt++) {
                int row = wm + mt * 16 + lrow;
                uint32_t addr = Ab + (uint32_t)row * 128u
                              + (uint32_t)((kb + lkhi) ^ ((row & 7) * 16));
                LDSM4(a[mt], addr);
            }
            #pragma unroll
            for (int np = 0; np < 4; np++) {
                int row = wn + np * 16 + lrow;
                uint32_t addr = Bb + (uint32_t)row * 128u
                              + (uint32_t)((kb + lkhi) ^ ((row & 7) * 16));
                LDSM4(b[np], addr);
            }
            #pragma unroll
            for (int mt = 0; mt < 4; mt++)
                #pragma unroll
                for (int nt = 0; nt < 8; nt++) {
                    const int np = nt >> 1, sel = nt & 1;
                    MMA16816(acc[mt][nt], a[mt], b[np][sel], b[np][sel + 2]);
                }
        }
    }

    // epilogue
    #pragma unroll
    for (int mt = 0; mt < 4; mt++) {
        const int r0 = bm + wm + mt * 16 + (lane >> 2);
        #pragma unroll
        for (int nt = 0; nt < 8; nt++) {
            const int c = bn + wn + nt * 8 + (lane & 3) * 2;
            float vx0 = acc[mt][nt][0], vy0 = acc[mt][nt][1];
            float vx1 = acc[mt][nt][2], vy1 = acc[mt][nt][3];
            if (EPI == 1) {
                float2 bvv = *(const float2*)&bias[c];
                vx0 += bvv.x; vy0 += bvv.y; vx1 += bvv.x; vy1 += bvv.y;
                vx0 = (vx0 > 15.f) ? vx0 : log1pf(__expf(vx0));
                vy0 = (vy0 > 15.f) ? vy0 : log1pf(__expf(vy0));
                vx1 = (vx1 > 15.f) ? vx1 : log1pf(__expf(vx1));
                vy1 = (vy1 > 15.f) ? vy1 : log1pf(__expf(vy1));
            } else if (EPI == 2) {
                float2 r0v = *(const float2*)&res[(size_t)r0 * N + c];
                float2 r1v = *(const float2*)&res[(size_t)(r0 + 8) * N + c];
                vx0 += r0v.x; vy0 += r0v.y; vx1 += r1v.x; vy1 += r1v.y;
            }
            *(float2*)&C[(size_t)r0 * N + c]       = make_float2(vx0, vy0);
            *(float2*)&C[(size_t)(r0 + 8) * N + c] = make_float2(vx1, vy1);
        }
    }
}

// ---------------- depthwise causal conv (K=4) + SiLU ----------------
__global__ void __launch_bounds__(256) conv_kernel(
    const float* __restrict__ xz, const float* __restrict__ cw,
    const float* __restrict__ cb, float* __restrict__ xp,
    __nv_bfloat16* __restrict__ xp16)
{
    size_t idx = (size_t)blockIdx.x * 256 + threadIdx.x;
    int d = (int)(idx & (DINNER - 1));
    size_t bl = idx >> 11;
    int l = (int)(bl & (LLEN - 1));
    const float4 wv = *(const float4*)&cw[d * 4];
    float acc = cb[d];
    size_t base = bl * (size_t)(2 * DINNER) + d;
    acc = fmaf(xz[base], wv.w, acc);
    if (l >= 1) acc = fmaf(xz[base - 1 * 2 * DINNER], wv.z, acc);
    if (l >= 2) acc = fmaf(xz[base - 2 * 2 * DINNER], wv.y, acc);
    if (l >= 3) acc = fmaf(xz[base - 3 * 2 * DINNER], wv.x, acc);
    float v = fsilu(acc);
    xp[idx] = v;
    xp16[idx] = __float2bfloat16(v);
}

// ---------------- B and C projections ----------------
__global__ void __launch_bounds__(256) bc_kernel(
    const float* __restrict__ xp, const float* __restrict__ Wb,
    const float* __restrict__ Wc, float* __restrict__ Bm, float* __restrict__ Cm)
{
    __shared__ float sW[64][32];
    __shared__ float sX[16][64];
    const int tid = threadIdx.x;
    const int row0 = blockIdx.x * 16;
    const int col = tid & 31;
    const int rg  = tid >> 5;
    float acc0 = 0.f, acc1 = 0.f;
    for (int k0 = 0; k0 < DINNER; k0 += 64) {
        __syncthreads();
        #pragma unroll
        for (int i = 0; i < 8; i++) {
            int e = tid * 8 + i;
            int kk = e >> 5, cc = e & 31;
            sW[kk][cc] = (cc < 16) ? Wb[(size_t)(k0 + kk) * 16 + cc]
                                   : Wc[(size_t)(k0 + kk) * 16 + cc - 16];
        }
        {
            int e = tid * 4; int r = e >> 6; int kk = e & 63;
            *(float4*)&sX[r][kk] = *(const float4*)&xp[(size_t)(row0 + r) * DINNER + k0 + kk];
        }
        __syncthreads();
        #pragma unroll
        for (int kk = 0; kk < 64; kk++) {
            float w = sW[kk][col];
            acc0 = fmaf(sX[rg][kk],     w, acc0);
            acc1 = fmaf(sX[rg + 8][kk], w, acc1);
        }
    }
    if (col < 16) {
        Bm[(size_t)(row0 + rg)     * 16 + col] = acc0;
        Bm[(size_t)(row0 + rg + 8) * 16 + col] = acc1;
    } else {
        Cm[(size_t)(row0 + rg)     * 16 + col - 16] = acc0;
        Cm[(size_t)(row0 + rg + 8) * 16 + col - 16] = acc1;
    }
}

// ---------------- selective scan, states split 4-way across threads ----------------
// Block: 128 thr = 32 d-groups x 4 subthreads (4 states each). Grid (BSZ, DINNER/32).
__global__ void __launch_bounds__(128) scan_kernel(
    const float* __restrict__ xp, const float* __restrict__ delta,
    const float* __restrict__ Bm, const float* __restrict__ Cm,
    const float* __restrict__ A_log, const float* __restrict__ Dp,
    const float* __restrict__ xz, __nv_bfloat16* __restrict__ u)
{
    const int b   = blockIdx.x;
    const int tid = threadIdx.x;
    const int g   = tid >> 2;          // d-group 0..31
    const int sub = tid & 3;
    const int d0  = blockIdx.y * 32;
    const int d   = d0 + g;
    const int n0  = sub * 4;

    __shared__ float sdt[2][8][32];
    __shared__ float sxt[2][8][32];
    __shared__ float szv[2][8][32];
    __shared__ float sBC[2][8][32];    // [B0..15 | C0..15]

    float A[4];
    #pragma unroll
    for (int i = 0; i < 4; i++) A[i] = -__expf(A_log[(size_t)d * NSTATE + n0 + i]);
    float h[4] = {0.f, 0.f, 0.f, 0.f};
    const float Dd = Dp[d];

    const size_t rowbase = (size_t)b * LLEN;

    // stage chunk 0: each thread loads 2 elements per array (8 steps x 32 = 256 / 128 thr)
    #pragma unroll
    for (int j = 0; j < 2; j++) {
        int idx = tid + j * 128;
        int s = idx >> 5, dd = idx & 31;
        size_t r = rowbase + s;
        sdt[0][s][dd] = delta[r * DINNER + d0 + dd];
        sxt[0][s][dd] = xp[r * DINNER + d0 + dd];
        szv[0][s][dd] = xz[r * (2 * DINNER) + DINNER + d0 + dd];
        sBC[0][s][dd] = (dd < 16) ? Bm[r * 16 + dd] : Cm[r * 16 + dd - 16];
    }
    __syncthreads();

    const int NCH = LLEN / 8;
    for (int c = 0; c < NCH; c++) {
        const int cur = c & 1, nxt = cur ^ 1;
        float pdt[2], pxt[2], pz[2], pbc[2];
        if (c + 1 < NCH) {
            size_t l1 = (size_t)(c + 1) * 8;
            #pragma unroll
            for (int j = 0; j < 2; j++) {
                int idx = tid + j * 128;
                int s = idx >> 5, dd = idx & 31;
                size_t r = rowbase + l1 + s;
                pdt[j] = delta[r * DINNER + d0 + dd];
                pxt[j] = xp[r * DINNER + d0 + dd];
                pz[j]  = xz[r * (2 * DINNER) + DINNER + d0 + dd];
                pbc[j] = (dd < 16) ? Bm[r * 16 + dd] : Cm[r * 16 + dd - 16];
            }
        }
        #pragma unroll
        for (int s = 0; s < 8; s++) {
            float dt = sdt[cur][s][g];
            float xt = sxt[cur][s][g];
            float4 Bv = *(const float4*)&sBC[cur][s][n0];
            float4 Cv = *(const float4*)&sBC[cur][s][16 + n0];
            float dx = dt * xt;
            float y = 0.f;
            float ab0 = __expf(dt * A[0]);
            float ab1 = __expf(dt * A[1]);
            float ab2 = __expf(dt * A[2]);
            float ab3 = __expf(dt * A[3]);
            h[0] = fmaf(ab0, h[0], dx * Bv.x);
            h[1] = fmaf(ab1, h[1], dx * Bv.y);
            h[2] = fmaf(ab2, h[2], dx * Bv.z);
            h[3] = fmaf(ab3, h[3], dx * Bv.w);
            y = fmaf(h[0], Cv.x, y);
            y = fmaf(h[1], Cv.y, y);
            y = fmaf(h[2], Cv.z, y);
            y = fmaf(h[3], Cv.w, y);
            y += __shfl_xor_sync(0xffffffffu, y, 1);
            y += __shfl_xor_sync(0xffffffffu, y, 2);
            if (sub == 0) {
                float yv = fmaf(Dd, xt, y);
                float zv = szv[cur][s][g];
                size_t r = rowbase + (size_t)c * 8 + s;
                u[r * DINNER + d] = __float2bfloat16(yv * fsilu(zv));
            }
        }
        if (c + 1 < NCH) {
            #pragma unroll
            for (int j = 0; j < 2; j++) {
                int idx = tid + j * 128;
                int s = idx >> 5, dd = idx & 31;
                sdt[nxt][s][dd] = pdt[j];
                sxt[nxt][s][dd] = pxt[j];
                szv[nxt][s][dd] = pz[j];
                sBC[nxt][s][dd] = pbc[j];
            }
        }
        __syncthreads();
    }
}

// ---------------- launch ----------------
#define GEMM_SMEM (4 * 49152)   // 4 stages x (16KB A + 32KB B) = 192KB

extern "C" void kernel_launch(void* const* d_in, const int* in_sizes, int n_in,
                              void* d_out, int out_size)
{
    const float* x       = (const float*)d_in[0];
    const float* norm_w  = (const float*)d_in[1];
    const float* norm_b  = (const float*)d_in[2];
    const float* W_in    = (const float*)d_in[3];
    const float* conv_w  = (const float*)d_in[4];
    const float* conv_b  = (const float*)d_in[5];
    const float* A_log   = (const float*)d_in[6];
    const float* W_b     = (const float*)d_in[7];
    const float* W_c     = (const float*)d_in[8];
    const float* W_delta = (const float*)d_in[9];
    const float* b_delta = (const float*)d_in[10];
    const float* D_param = (const float*)d_in[11];
    const float* W_out   = (const float*)d_in[12];
    float* out = (float*)d_out;

    float *xz, *xp, *dl, *Bm, *Cm;
    __nv_bfloat16 *xn16, *xp16, *u16, *wtin, *wtdl, *wtout;
    cudaGetSymbolAddress((void**)&xz, g_xz);
    cudaGetSymbolAddress((void**)&xp, g_xp);
    cudaGetSymbolAddress((void**)&dl, g_dl);
    cudaGetSymbolAddress((void**)&Bm, g_Bm);
    cudaGetSymbolAddress((void**)&Cm, g_Cm);
    cudaGetSymbolAddress((void**)&xn16, g_xn16);
    cudaGetSymbolAddress((void**)&xp16, g_xp16);
    cudaGetSymbolAddress((void**)&u16, g_u16);
    cudaGetSymbolAddress((void**)&wtin, g_wtin);
    cudaGetSymbolAddress((void**)&wtdl, g_wtdl);
    cudaGetSymbolAddress((void**)&wtout, g_wtout);

    cudaFuncSetAttribute(gemm_mma<0>, cudaFuncAttributeMaxDynamicSharedMemorySize, GEMM_SMEM);
    cudaFuncSetAttribute(gemm_mma<1>, cudaFuncAttributeMaxDynamicSharedMemorySize, GEMM_SMEM);
    cudaFuncSetAttribute(gemm_mma<2>, cudaFuncAttributeMaxDynamicSharedMemorySize, GEMM_SMEM);

    // 0) weight transpose + convert to bf16
    wt_kernel<<<dim3(2 * DINNER / 32, DMODEL / 32), 256>>>(W_in, wtin, DMODEL, 2 * DINNER);
    wt_kernel<<<dim3(DINNER / 32, DINNER / 32), 256>>>(W_delta, wtdl, DINNER, DINNER);
    wt_kernel<<<dim3(DMODEL / 32, DINNER / 32), 256>>>(W_out, wtout, DINNER, DMODEL);

    // 1) layernorm (bf16 out)
    ln_kernel<<<MROWS, 256>>>(x, norm_w, norm_b, xn16);
    // 2) in-proj: [8192,1024] @ [1024,4096]
    gemm_mma<0><<<dim3(2 * DINNER / 256, MROWS / 128), 256, GEMM_SMEM>>>(
        xn16, wtin, xz, MROWS, 2 * DINNER, DMODEL, nullptr, nullptr);
    // 3) depthwise causal conv + silu
    conv_kernel<<<(MROWS * DINNER) / 256, 256>>>(xz, conv_w, conv_b, xp, xp16);
    // 4) delta: softplus([8192,2048] @ [2048,2048] + b)
    gemm_mma<1><<<dim3(DINNER / 256, MROWS / 128), 256, GEMM_SMEM>>>(
        xp16, wtdl, dl, MROWS, DINNER, DINNER, b_delta, nullptr);
    // 5) B and C projections
    bc_kernel<<<MROWS / 16, 256>>>(xp, W_b, W_c, Bm, Cm);
    // 6) selective scan (4-way state split) fused with y*silu(z)
    scan_kernel<<<dim3(BSZ, DINNER / 32), 128>>>(xp, dl, Bm, Cm, A_log, D_param, xz, u16);
    // 7) out-proj + residual: [8192,2048] @ [2048,1024] + x
    gemm_mma<2><<<dim3(DMODEL / 256, MROWS / 128), 256, GEMM_SMEM>>>(
        u16, wtout, out, MROWS, DMODEL, DINNER, nullptr, x);
}